// round 3
// baseline (speedup 1.0000x reference)
#include <cuda_runtime.h>

// R3: 512-thread fused 2-layer LSTM, weights-in-regs (k-split), reduce-scatter
// activations (each lane owns a distinct batch after k-reduction), pitch-100
// bank-conflict-free hcat. 147 CTAs x 512 thr, 14 batch/CTA (padded to 16).

typedef unsigned long long u64;

#define TT     512
#define NBR    14        // real batch rows per CTA
#define NBP    16        // padded rows in smem
#define NTH    512
#define BTOT   2048
#define NCTA   147
#define PITCH  100       // floats per hcat row (100 % 32 == 4 -> conflict-free)

__device__ __forceinline__ u64 pack2(float lo, float hi) {
    u64 r; asm("mov.b64 %0, {%1, %2};" : "=l"(r) : "f"(lo), "f"(hi)); return r;
}
__device__ __forceinline__ float2 unpack2(u64 a) {
    float2 r; asm("mov.b64 {%0, %1}, %2;" : "=f"(r.x), "=f"(r.y) : "l"(a)); return r;
}
__device__ __forceinline__ void fma2(u64 &d, u64 a, u64 b) {
    asm("fma.rn.f32x2 %0, %1, %2, %0;" : "+l"(d) : "l"(a), "l"(b));
}
__device__ __forceinline__ u64 add2(u64 a, u64 b) {
    u64 r; asm("add.rn.f32x2 %0, %1, %2;" : "=l"(r) : "l"(a), "l"(b)); return r;
}
__device__ __forceinline__ u64 shflx2(u64 v, int m) {
    return __shfl_xor_sync(0xffffffffu, v, m);
}
__device__ __forceinline__ float ex2f(float x) {
    float r; asm("ex2.approx.f32 %0, %1;" : "=f"(r) : "f"(x)); return r;
}
__device__ __forceinline__ float rcpf(float x) {
    float r; asm("rcp.approx.f32 %0, %1;" : "=f"(r) : "f"(x)); return r;
}
#define LOG2E 1.44269504f

__global__ __launch_bounds__(NTH, 1)
void lstm_fused(const float* __restrict__ x,
                const float* __restrict__ Wih1, const float* __restrict__ Whh1,
                const float* __restrict__ bih1, const float* __restrict__ bhh1,
                const float* __restrict__ Wih2, const float* __restrict__ Whh2,
                const float* __restrict__ bih2, const float* __restrict__ bhh2,
                const float* __restrict__ fc1w, const float* __restrict__ fc1b,
                const float* __restrict__ fc2w, const float* __restrict__ fc2b,
                float* __restrict__ out)
{
    // hcat row = [h1(64) | h2(32) | pad(4)], double-buffered, 16 rows.
    __shared__ __align__(16) float hcat[2][NBP][PITCH];
    __shared__ __align__(16) float xbuf[NBP][4];
    __shared__ float sfc1w[512], sfc1b[16], sfc2w[16], sfc2b[1];

    const int tid = threadIdx.x;
    const int b0  = blockIdx.x * NBR;
    const bool bvalid = (tid < NBR) && (b0 + tid < BTOT);

    // L1 roles: kh = k-half, g1 = gate, j1 = hidden unit
    const int kh = tid & 1;
    const int g1 = (tid >> 1) & 3;
    const int j1 = tid >> 3;
    // L2 roles: kq = k-quarter, g2 = gate, j2 = hidden unit
    const int kq = tid & 3;
    const int g2 = (tid >> 2) & 3;
    const int j2 = tid >> 4;

    // ---- weights -> registers ----
    u64 w1[16], wx, w2[12];
    float bias1, bias2;
    {
        const int r1 = g1 * 64 + j1;
        const float2* Wp = (const float2*)(Whh1 + (size_t)r1 * 64) + kh * 16;
        #pragma unroll
        for (int m = 0; m < 16; ++m) { float2 v = Wp[m]; w1[m] = pack2(v.x, v.y); }
        float2 xv = *(const float2*)(Wih1 + (size_t)r1 * 4 + 2 * kh);
        wx = pack2(xv.x, xv.y);
        bias1 = bih1[r1] + bhh1[r1];
    }
    {
        const int r2 = g2 * 32 + j2;
        #pragma unroll
        for (int m = 0; m < 12; ++m) {
            int k = kq * 24 + 2 * m;   // concat k: [0,64)=h1 via Wih2, [64,96)=h2 via Whh2
            float lo, hi;
            if (k < 64) { lo = Wih2[r2 * 64 + k];        hi = Wih2[r2 * 64 + k + 1]; }
            else        { lo = Whh2[r2 * 32 + (k - 64)]; hi = Whh2[r2 * 32 + (k - 63)]; }
            w2[m] = pack2(lo, hi);
        }
        bias2 = bih2[r2] + bhh2[r2];
    }
    // activation constants (gate 2 = tanh, else sigmoid = 0.5*tanh(x/2)+0.5)
    const float pm1 = (g1 == 2) ? 2.f * LOG2E : LOG2E;
    const float am1 = (g1 == 2) ? 1.f : 0.5f;
    const float ab1 = (g1 == 2) ? 0.f : 0.5f;
    const float pm2 = (g2 == 2) ? 2.f * LOG2E : LOG2E;
    const float am2 = (g2 == 2) ? 1.f : 0.5f;
    const float ab2 = (g2 == 2) ? 0.f : 0.5f;

    // ---- smem init ----
    for (int i = tid; i < 2 * NBP * PITCH; i += NTH) ((float*)hcat)[i] = 0.f;
    for (int i = tid; i < NBP * 4;         i += NTH) ((float*)xbuf)[i] = 0.f;
    for (int i = tid; i < 512;             i += NTH) sfc1w[i] = fc1w[i];
    if (tid < 16) sfc1b[tid] = fc1b[tid];
    if (tid < 16) sfc2w[tid] = fc2w[tid];
    if (tid == 0) sfc2b[0] = fc2b[0];
    __syncthreads();

    float c1[7]  = {0.f, 0.f, 0.f, 0.f, 0.f, 0.f, 0.f};
    float c2[4]  = {0.f, 0.f, 0.f, 0.f};

    float4 xreg = make_float4(0.f, 0.f, 0.f, 0.f);
    if (bvalid) xreg = *(const float4*)(x + (size_t)(b0 + tid) * TT * 4);

    int cur = 0;
    for (int t = 0; t < TT; ++t) {
        const int nxt = cur ^ 1;

        if (tid < NBR) {
            *(float4*)&xbuf[tid][0] = xreg;
            if (bvalid && t + 1 < TT)
                xreg = *(const float4*)(x + ((size_t)(b0 + tid) * TT + t + 1) * 4);
        }
        __syncthreads();

        // ---------- Layer 1: 7 groups of 2 batches ----------
        #pragma unroll
        for (int G = 0; G < 7; ++G) {
            const int bo = 2 * G + kh;        // batch this lane will own
            const int bx = 2 * G + (kh ^ 1);  // partner batch
            u64 p0 = pack2(bias1, 0.f), p1 = 0ULL;
            const ulonglong2* ho = (const ulonglong2*)&hcat[cur][bo][kh * 32];
            const ulonglong2* hx = (const ulonglong2*)&hcat[cur][bx][kh * 32];
            fma2(p0, wx, *(const u64*)&xbuf[bo][2 * kh]);
            fma2(p1, wx, *(const u64*)&xbuf[bx][2 * kh]);
            #pragma unroll
            for (int m = 0; m < 8; ++m) {
                ulonglong2 A = ho[m];
                ulonglong2 B = hx[m];
                fma2(p0, w1[2 * m],     A.x);
                fma2(p1, w1[2 * m],     B.x);
                fma2(p0, w1[2 * m + 1], A.y);
                fma2(p1, w1[2 * m + 1], B.y);
            }
            p0 = add2(p0, shflx2(p1, 1));     // lane now has full sum for bo
            float2 f = unpack2(p0);
            float raw = f.x + f.y;

            float ev = ex2f(pm1 * raw);
            float th = fmaf(-2.f, rcpf(ev + 1.f), 1.f);
            float a  = fmaf(am1, th, ab1);               // own gate, batch bo
            float v2 = __shfl_xor_sync(0xffffffffu, a, 4);  // i<->g~, f<->o
            float p  = a * v2;
            float pv = __shfl_xor_sync(0xffffffffu, p, 2);  // f-lane gets i*g~
            if (g1 == 1) {
                float cn = fmaf(a, c1[G], pv);
                c1[G] = cn;
                float e2 = ex2f(2.f * LOG2E * cn);
                float tc = fmaf(-2.f, rcpf(e2 + 1.f), 1.f);
                hcat[nxt][bo][j1] = v2 * tc;             // o * tanh(c)
            }
        }
        __syncthreads();

        // ---------- Layer 2: 4 groups of 4 batches (b=14,15 are padding) ----------
        #pragma unroll
        for (int G = 0; G < 4; ++G) {
            const int a0b = 4 * G + kq;
            const int a1b = 4 * G + (kq ^ 1);
            const int a2b = 4 * G + (kq ^ 2);
            const int a3b = 4 * G + (kq ^ 3);
            u64 p0 = pack2(bias2, 0.f), p1 = 0ULL, p2 = 0ULL, p3 = 0ULL;
            const ulonglong2* h0 = (const ulonglong2*)&hcat[nxt][a0b][kq * 24];
            const ulonglong2* h1 = (const ulonglong2*)&hcat[nxt][a1b][kq * 24];
            const ulonglong2* h2 = (const ulonglong2*)&hcat[nxt][a2b][kq * 24];
            const ulonglong2* h3 = (const ulonglong2*)&hcat[nxt][a3b][kq * 24];
            #pragma unroll
            for (int m = 0; m < 6; ++m) {
                ulonglong2 A = h0[m], B = h1[m], C = h2[m], D = h3[m];
                fma2(p0, w2[2 * m],     A.x); fma2(p0, w2[2 * m + 1], A.y);
                fma2(p1, w2[2 * m],     B.x); fma2(p1, w2[2 * m + 1], B.y);
                fma2(p2, w2[2 * m],     C.x); fma2(p2, w2[2 * m + 1], C.y);
                fma2(p3, w2[2 * m],     D.x); fma2(p3, w2[2 * m + 1], D.y);
            }
            // reduce-scatter: lane kq ends with full sum for batch a0b
            p0 = add2(p0, shflx2(p1, 1));
            u64 tt = add2(p2, shflx2(p3, 1));
            p0 = add2(p0, shflx2(tt, 2));
            float2 f = unpack2(p0);
            float raw = f.x + f.y;

            float ev = ex2f(pm2 * raw);
            float th = fmaf(-2.f, rcpf(ev + 1.f), 1.f);
            float a  = fmaf(am2, th, ab2);
            float v2 = __shfl_xor_sync(0xffffffffu, a, 8);
            float p  = a * v2;
            float pv = __shfl_xor_sync(0xffffffffu, p, 4);
            if (g2 == 1) {
                float cn = fmaf(a, c2[G], pv);
                c2[G] = cn;
                float e2 = ex2f(2.f * LOG2E * cn);
                float tc = fmaf(-2.f, rcpf(e2 + 1.f), 1.f);
                hcat[cur][a0b][64 + j2] = v2 * tc;       // h2_t for step t+1
            }
        }
        cur = nxt;
    }

    __syncthreads();

    // ---- FC head on final h2 (written into hcat[(TT-1)&1]) ----
    if (bvalid) {
        const float* hv = &hcat[(TT - 1) & 1][tid][64];
        float o = sfc2b[0];
        #pragma unroll
        for (int f = 0; f < 16; ++f) {
            float acc = sfc1b[f];
            #pragma unroll
            for (int k = 0; k < 32; ++k)
                acc = fmaf(sfc1w[f * 32 + k], hv[k], acc);
            o = fmaf(sfc2w[f], fmaxf(acc, 0.f), o);
        }
        out[b0 + tid] = o;
    }
}

extern "C" void kernel_launch(void* const* d_in, const int* in_sizes, int n_in,
                              void* d_out, int out_size) {
    const float* x    = (const float*)d_in[0];
    const float* Wih1 = (const float*)d_in[1];
    const float* Whh1 = (const float*)d_in[2];
    const float* bih1 = (const float*)d_in[3];
    const float* bhh1 = (const float*)d_in[4];
    const float* Wih2 = (const float*)d_in[5];
    const float* Whh2 = (const float*)d_in[6];
    const float* bih2 = (const float*)d_in[7];
    const float* bhh2 = (const float*)d_in[8];
    const float* fc1w = (const float*)d_in[9];
    const float* fc1b = (const float*)d_in[10];
    const float* fc2w = (const float*)d_in[11];
    const float* fc2b = (const float*)d_in[12];
    float* out = (float*)d_out;

    lstm_fused<<<NCTA, NTH>>>(x, Wih1, Whh1, bih1, bhh1,
                              Wih2, Whh2, bih2, bhh2,
                              fc1w, fc1b, fc2w, fc2b, out);
}

// round 4
// speedup vs baseline: 1.4229x; 1.4229x over previous
#include <cuda_runtime.h>

// R4: gate-local lanes (j, all 4 gates, k-slice), reduce-scatter over k-slices
// so each lane owns a distinct batch; no gate dance; weights in registers;
// minimal broadcast LDS. 147 CTAs x 256 thr, 14 batch/CTA (padded 16).

typedef unsigned long long u64;

#define TT     512
#define NBR    14
#define NBP    16
#define NTH    256
#define BTOT   2048
#define NCTA   147
#define PITCH  104     // floats per hcat row; 104%32=8 -> verified conflict-free

__device__ __forceinline__ u64 pack2(float lo, float hi) {
    u64 r; asm("mov.b64 %0, {%1, %2};" : "=l"(r) : "f"(lo), "f"(hi)); return r;
}
__device__ __forceinline__ float2 unpack2(u64 a) {
    float2 r; asm("mov.b64 {%0, %1}, %2;" : "=f"(r.x), "=f"(r.y) : "l"(a)); return r;
}
__device__ __forceinline__ void fma2(u64 &d, u64 a, u64 b) {
    asm("fma.rn.f32x2 %0, %1, %2, %0;" : "+l"(d) : "l"(a), "l"(b));
}
__device__ __forceinline__ u64 add2(u64 a, u64 b) {
    u64 r; asm("add.rn.f32x2 %0, %1, %2;" : "=l"(r) : "l"(a), "l"(b)); return r;
}
__device__ __forceinline__ u64 shflx2(u64 v, int m) {
    return __shfl_xor_sync(0xffffffffu, v, m);
}
__device__ __forceinline__ float ex2f(float x) {
    float r; asm("ex2.approx.f32 %0, %1;" : "=f"(r) : "f"(x)); return r;
}
__device__ __forceinline__ float rcpf(float x) {
    float r; asm("rcp.approx.f32 %0, %1;" : "=f"(r) : "f"(x)); return r;
}
#define LOG2E 1.44269504f
__device__ __forceinline__ float sigf(float x) {
    return rcpf(1.f + ex2f(-LOG2E * x));
}
__device__ __forceinline__ float tanhv(float x) {
    return fmaf(-2.f, rcpf(ex2f(2.f * LOG2E * x) + 1.f), 1.f);
}

__global__ __launch_bounds__(NTH, 1)
void lstm_fused(const float* __restrict__ x,
                const float* __restrict__ Wih1, const float* __restrict__ Whh1,
                const float* __restrict__ bih1, const float* __restrict__ bhh1,
                const float* __restrict__ Wih2, const float* __restrict__ Whh2,
                const float* __restrict__ bih2, const float* __restrict__ bhh2,
                const float* __restrict__ fc1w, const float* __restrict__ fc1b,
                const float* __restrict__ fc2w, const float* __restrict__ fc2b,
                float* __restrict__ out)
{
    // hcat row = [h1(64) | h2(32) | pad(8)], double-buffered.
    __shared__ __align__(16) float hcat[2][NBP][PITCH];
    __shared__ __align__(16) float xbuf[NBP][4];
    __shared__ float sfc1w[512], sfc1b[16], sfc2w[16], sfc2b[1];

    const int tid  = threadIdx.x;
    const int lane = tid & 31;
    const int wg   = tid >> 5;             // 0..7
    const int b0   = blockIdx.x * NBR;
    const bool bvalid = (tid < NBR) && (b0 + tid < BTOT);

    // L1 roles: lane = jslot(3b) | ks1(2b).  j1 = wg*8 + jslot, k-quarter ks1.
    const int jslot = lane & 7;
    const int ks1   = lane >> 3;           // 0..3
    const int j1    = wg * 8 + jslot;
    // L2 roles: lane = js2(2b) | ks2(3b).  j2 = wg*4 + js2, k-eighth ks2.
    const int js2 = lane & 3;
    const int ks2 = (lane >> 2) & 7;       // 0..7
    const int q2  = ks2 & 3;               // scatter bits
    const int j2  = wg * 4 + js2;

    // ---- weights -> registers ----
    u64 w1[4][8], wx[4][2], w2[4][6];
    float b1r[4], b2r[4];
    #pragma unroll
    for (int g = 0; g < 4; ++g) {
        const int r1 = g * 64 + j1;
        #pragma unroll
        for (int m = 0; m < 8; ++m) {
            int k = 16 * ks1 + 2 * m;
            w1[g][m] = pack2(Whh1[r1 * 64 + k], Whh1[r1 * 64 + k + 1]);
        }
        wx[g][0] = pack2(Wih1[r1 * 4 + 0], Wih1[r1 * 4 + 1]);
        wx[g][1] = pack2(Wih1[r1 * 4 + 2], Wih1[r1 * 4 + 3]);
        b1r[g] = bih1[r1] + bhh1[r1];

        const int r2 = g * 32 + j2;
        #pragma unroll
        for (int m = 0; m < 6; ++m) {
            int k = 12 * ks2 + 2 * m;     // concat: [0,64)=h1 (Wih2), [64,96)=h2 (Whh2)
            float lo = (k < 64)     ? Wih2[r2 * 64 + k]     : Whh2[r2 * 32 + k - 64];
            float hi = (k + 1 < 64) ? Wih2[r2 * 64 + k + 1] : Whh2[r2 * 32 + k - 63];
            w2[g][m] = pack2(lo, hi);
        }
        b2r[g] = bih2[r2] + bhh2[r2];
    }

    // ---- smem init ----
    for (int i = tid; i < 2 * NBP * PITCH; i += NTH) ((float*)hcat)[i] = 0.f;
    for (int i = tid; i < NBP * 4;         i += NTH) ((float*)xbuf)[i] = 0.f;
    for (int i = tid; i < 512;             i += NTH) sfc1w[i] = fc1w[i];
    if (tid < 16) sfc1b[tid] = fc1b[tid];
    if (tid < 16) sfc2w[tid] = fc2w[tid];
    if (tid == 0) sfc2b[0] = fc2b[0];
    __syncthreads();

    float c1[4] = {0.f, 0.f, 0.f, 0.f};   // owned batch 4G + ks1
    float c2[4] = {0.f, 0.f, 0.f, 0.f};   // owned batch 4G + q2

    float4 xreg = make_float4(0.f, 0.f, 0.f, 0.f);
    if (bvalid) xreg = *(const float4*)(x + (size_t)(b0 + tid) * TT * 4);

    int cur = 0;
    for (int t = 0; t < TT; ++t) {
        const int nxt = cur ^ 1;

        if (tid < NBR) {
            *(float4*)&xbuf[tid][0] = xreg;
            if (bvalid && t + 1 < TT)
                xreg = *(const float4*)(x + ((size_t)(b0 + tid) * TT + t + 1) * 4);
        }
        __syncthreads();

        // ---------------- Layer 1 ----------------
        #pragma unroll
        for (int G = 0; G < 4; ++G) {
            u64 acc[4][4];
            #pragma unroll
            for (int g = 0; g < 4; ++g)
                #pragma unroll
                for (int s = 0; s < 4; ++s) acc[g][s] = 0ULL;

            const float* hr[4];
            #pragma unroll
            for (int s = 0; s < 4; ++s)
                hr[s] = &hcat[cur][4 * G + (ks1 ^ s)][16 * ks1];

            if (ks1 == 0) {   // x contribution counted exactly once (slice 0)
                #pragma unroll
                for (int s = 0; s < 4; ++s) {
                    u64 xv0 = *(const u64*)&xbuf[4 * G + s][0];
                    u64 xv1 = *(const u64*)&xbuf[4 * G + s][2];
                    #pragma unroll
                    for (int g = 0; g < 4; ++g) {
                        fma2(acc[g][s], wx[g][0], xv0);
                        fma2(acc[g][s], wx[g][1], xv1);
                    }
                }
            }
            #pragma unroll
            for (int m = 0; m < 4; ++m) {
                #pragma unroll
                for (int s = 0; s < 4; ++s) {
                    ulonglong2 hh = *(const ulonglong2*)(hr[s] + m * 4);
                    #pragma unroll
                    for (int g = 0; g < 4; ++g) {
                        fma2(acc[g][s], w1[g][2 * m],     hh.x);
                        fma2(acc[g][s], w1[g][2 * m + 1], hh.y);
                    }
                }
            }
            // reduce-scatter over ks1 (lane bits 3,4): lane ends owning batch 4G+ks1
            float raw[4];
            #pragma unroll
            for (int g = 0; g < 4; ++g) {
                acc[g][0] = add2(acc[g][0], shflx2(acc[g][1], 8));
                u64 tt    = add2(acc[g][2], shflx2(acc[g][3], 8));
                acc[g][0] = add2(acc[g][0], shflx2(tt, 16));
                float2 f  = unpack2(acc[g][0]);
                raw[g] = f.x + f.y + b1r[g];
            }
            float gi = sigf(raw[0]);
            float gf = sigf(raw[1]);
            float gg = tanhv(raw[2]);
            float go = sigf(raw[3]);
            float c  = fmaf(gf, c1[G], gi * gg);
            c1[G] = c;
            hcat[nxt][4 * G + ks1][j1] = go * tanhv(c);
        }
        __syncthreads();

        // ---------------- Layer 2 ----------------
        #pragma unroll
        for (int G = 0; G < 4; ++G) {
            u64 acc[4][4];
            #pragma unroll
            for (int g = 0; g < 4; ++g)
                #pragma unroll
                for (int s = 0; s < 4; ++s) acc[g][s] = 0ULL;

            const float* hr[4];
            #pragma unroll
            for (int s = 0; s < 4; ++s)
                hr[s] = &hcat[nxt][4 * G + (q2 ^ s)][12 * ks2];

            #pragma unroll
            for (int m = 0; m < 3; ++m) {
                #pragma unroll
                for (int s = 0; s < 4; ++s) {
                    ulonglong2 hh = *(const ulonglong2*)(hr[s] + m * 4);
                    #pragma unroll
                    for (int g = 0; g < 4; ++g) {
                        fma2(acc[g][s], w2[g][2 * m],     hh.x);
                        fma2(acc[g][s], w2[g][2 * m + 1], hh.y);
                    }
                }
            }
            // scatter over q2 (lane bits 2,3), then all-reduce over bit 4
            float raw[4];
            #pragma unroll
            for (int g = 0; g < 4; ++g) {
                acc[g][0] = add2(acc[g][0], shflx2(acc[g][1], 4));
                u64 tt    = add2(acc[g][2], shflx2(acc[g][3], 4));
                acc[g][0] = add2(acc[g][0], shflx2(tt, 8));
                acc[g][0] = add2(acc[g][0], shflx2(acc[g][0], 16));
                float2 f  = unpack2(acc[g][0]);
                raw[g] = f.x + f.y + b2r[g];
            }
            float gi = sigf(raw[0]);
            float gf = sigf(raw[1]);
            float gg = tanhv(raw[2]);
            float go = sigf(raw[3]);
            float c  = fmaf(gf, c2[G], gi * gg);
            c2[G] = c;
            if (lane < 16)   // one copy (bit4==0) writes h2
                hcat[cur][4 * G + q2][64 + j2] = go * tanhv(c);
        }
        cur = nxt;
    }

    __syncthreads();

    // ---- FC head on final h2 ----
    if (bvalid) {
        const float* hv = &hcat[(TT - 1) & 1][tid][64];
        float o = sfc2b[0];
        #pragma unroll
        for (int f = 0; f < 16; ++f) {
            float acc = sfc1b[f];
            #pragma unroll
            for (int k = 0; k < 32; ++k)
                acc = fmaf(sfc1w[f * 32 + k], hv[k], acc);
            o = fmaf(sfc2w[f], fmaxf(acc, 0.f), o);
        }
        out[b0 + tid] = o;
    }
}

extern "C" void kernel_launch(void* const* d_in, const int* in_sizes, int n_in,
                              void* d_out, int out_size) {
    const float* x    = (const float*)d_in[0];
    const float* Wih1 = (const float*)d_in[1];
    const float* Whh1 = (const float*)d_in[2];
    const float* bih1 = (const float*)d_in[3];
    const float* bhh1 = (const float*)d_in[4];
    const float* Wih2 = (const float*)d_in[5];
    const float* Whh2 = (const float*)d_in[6];
    const float* bih2 = (const float*)d_in[7];
    const float* bhh2 = (const float*)d_in[8];
    const float* fc1w = (const float*)d_in[9];
    const float* fc1b = (const float*)d_in[10];
    const float* fc2w = (const float*)d_in[11];
    const float* fc2b = (const float*)d_in[12];
    float* out = (float*)d_out;

    lstm_fused<<<NCTA, NTH>>>(x, Wih1, Whh1, bih1, bhh1,
                              Wih2, Whh2, bih2, bhh2,
                              fc1w, fc1b, fc2w, fc2b, out);
}

// round 5
// speedup vs baseline: 2.0385x; 1.4326x over previous
#include <cuda_runtime.h>

// R5: R4 layout + scalar shuffle trees, tanh.approx activations (pre-halved
// sigmoid weights), slice-distributed x-term, compile-time SMEM addressing
// via 2-step unrolled loop. 147 CTAs x 256 thr.

typedef unsigned long long u64;

#define TT     512
#define NBR    14
#define NBP    16
#define NTH    256
#define BTOT   2048
#define NCTA   147
#define PITCH  104

__device__ __forceinline__ u64 pack2(float lo, float hi) {
    u64 r; asm("mov.b64 %0, {%1, %2};" : "=l"(r) : "f"(lo), "f"(hi)); return r;
}
__device__ __forceinline__ float2 unpack2(u64 a) {
    float2 r; asm("mov.b64 {%0, %1}, %2;" : "=f"(r.x), "=f"(r.y) : "l"(a)); return r;
}
__device__ __forceinline__ void fma2(u64 &d, u64 a, u64 b) {
    asm("fma.rn.f32x2 %0, %1, %2, %0;" : "+l"(d) : "l"(a), "l"(b));
}
__device__ __forceinline__ float tanhap(float x) {
    float r; asm("tanh.approx.f32 %0, %1;" : "=f"(r) : "f"(x)); return r;
}
__device__ __forceinline__ float shx(float v, int m) {
    return __shfl_xor_sync(0xffffffffu, v, m);
}

__global__ __launch_bounds__(NTH, 1)
void lstm_fused(const float* __restrict__ x,
                const float* __restrict__ Wih1, const float* __restrict__ Whh1,
                const float* __restrict__ bih1, const float* __restrict__ bhh1,
                const float* __restrict__ Wih2, const float* __restrict__ Whh2,
                const float* __restrict__ bih2, const float* __restrict__ bhh2,
                const float* __restrict__ fc1w, const float* __restrict__ fc1b,
                const float* __restrict__ fc2w, const float* __restrict__ fc2b,
                float* __restrict__ out)
{
    __shared__ __align__(16) float hcat[2][NBP][PITCH];
    __shared__ __align__(16) float xbuf[NBP][4];
    __shared__ float sfc1w[512], sfc1b[16], sfc2w[16], sfc2b[1];

    const int tid  = threadIdx.x;
    const int lane = tid & 31;
    const int wg   = tid >> 5;
    const int b0   = blockIdx.x * NBR;
    const bool bvalid = (tid < NBR) && (b0 + tid < BTOT);

    // L1 roles: lane = jslot(3b) | ks1(2b)
    const int jslot = lane & 7;
    const int ks1   = lane >> 3;
    const int j1    = wg * 8 + jslot;
    // L2 roles: lane = js2(2b) | ks2(3b)
    const int js2 = lane & 3;
    const int ks2 = (lane >> 2) & 7;
    const int q2  = ks2 & 3;
    const int j2  = wg * 4 + js2;

    // ---- weights -> registers (sigmoid gates pre-halved) ----
    u64 w1[4][8], w2[4][6];
    float wxs[4], b1r[4], b2r[4];
    #pragma unroll
    for (int g = 0; g < 4; ++g) {
        const float sc = (g == 2) ? 1.f : 0.5f;
        const int r1 = g * 64 + j1;
        #pragma unroll
        for (int m = 0; m < 8; ++m) {
            int k = 16 * ks1 + 2 * m;
            w1[g][m] = pack2(sc * Whh1[r1 * 64 + k], sc * Whh1[r1 * 64 + k + 1]);
        }
        wxs[g] = sc * Wih1[r1 * 4 + ks1];
        b1r[g] = sc * (bih1[r1] + bhh1[r1]);

        const int r2 = g * 32 + j2;
        #pragma unroll
        for (int m = 0; m < 6; ++m) {
            int k = 12 * ks2 + 2 * m;
            float lo = (k < 64)     ? Wih2[r2 * 64 + k]     : Whh2[r2 * 32 + k - 64];
            float hi = (k + 1 < 64) ? Wih2[r2 * 64 + k + 1] : Whh2[r2 * 32 + k - 63];
            w2[g][m] = pack2(sc * lo, sc * hi);
        }
        b2r[g] = sc * (bih2[r2] + bhh2[r2]);
    }

    // per-thread row offsets (float elements)
    int ro1[4], ro2[4], rox[4];
    #pragma unroll
    for (int s = 0; s < 4; ++s) {
        ro1[s] = (ks1 ^ s) * PITCH + 16 * ks1;
        ro2[s] = (q2  ^ s) * PITCH + 12 * ks2;
        rox[s] = (ks1 ^ s) * 4 + ks1;
    }
    const int so1 = ks1 * PITCH + j1;
    const int so2 = q2 * PITCH + 64 + j2;

    // ---- smem init ----
    for (int i = tid; i < 2 * NBP * PITCH; i += NTH) ((float*)hcat)[i] = 0.f;
    for (int i = tid; i < NBP * 4;         i += NTH) ((float*)xbuf)[i] = 0.f;
    for (int i = tid; i < 512;             i += NTH) sfc1w[i] = fc1w[i];
    if (tid < 16) sfc1b[tid] = fc1b[tid];
    if (tid < 16) sfc2w[tid] = fc2w[tid];
    if (tid == 0) sfc2b[0] = fc2b[0];
    __syncthreads();

    float c1[4] = {0.f, 0.f, 0.f, 0.f};
    float c2[4] = {0.f, 0.f, 0.f, 0.f};

    float4 xreg = make_float4(0.f, 0.f, 0.f, 0.f);
    if (bvalid) xreg = *(const float4*)(x + (size_t)(b0 + tid) * TT * 4);

    auto step = [&](float (&A)[NBP][PITCH], float (&B)[NBP][PITCH], int t) {
        if (tid < NBR) {
            *(float4*)&xbuf[tid][0] = xreg;
            if (bvalid && t + 1 < TT)
                xreg = *(const float4*)(x + ((size_t)(b0 + tid) * TT + t + 1) * 4);
        }
        __syncthreads();

        const float* Ab = &A[0][0];
        float*       Bb = &B[0][0];
        const float* Xb = &xbuf[0][0];

        // ---------------- Layer 1: read A[0..64), write B[j1] ----------------
        #pragma unroll
        for (int G = 0; G < 4; ++G) {
            u64 acc[4][4];
            #pragma unroll
            for (int g = 0; g < 4; ++g)
                #pragma unroll
                for (int s = 0; s < 4; ++s) acc[g][s] = 0ULL;

            #pragma unroll
            for (int m = 0; m < 4; ++m)
                #pragma unroll
                for (int s = 0; s < 4; ++s) {
                    ulonglong2 hh =
                        *(const ulonglong2*)(Ab + 4 * G * PITCH + ro1[s] + 4 * m);
                    #pragma unroll
                    for (int g = 0; g < 4; ++g) {
                        fma2(acc[g][s], w1[g][2 * m],     hh.x);
                        fma2(acc[g][s], w1[g][2 * m + 1], hh.y);
                    }
                }

            float xv[4];
            #pragma unroll
            for (int s = 0; s < 4; ++s) xv[s] = Xb[16 * G + rox[s]];

            float raw[4];
            #pragma unroll
            for (int g = 0; g < 4; ++g) {
                float r0, r1, r2, r3;
                { float2 f = unpack2(acc[g][0]); r0 = f.x + f.y; }
                { float2 f = unpack2(acc[g][1]); r1 = f.x + f.y; }
                { float2 f = unpack2(acc[g][2]); r2 = f.x + f.y; }
                { float2 f = unpack2(acc[g][3]); r3 = f.x + f.y; }
                r0 = fmaf(wxs[g], xv[0], r0);
                r1 = fmaf(wxs[g], xv[1], r1);
                r2 = fmaf(wxs[g], xv[2], r2);
                r3 = fmaf(wxs[g], xv[3], r3);
                float t1 = r0 + shx(r1, 8);
                float t2 = r2 + shx(r3, 8);
                raw[g] = t1 + shx(t2, 16) + b1r[g];
            }
            float gi = fmaf(0.5f, tanhap(raw[0]), 0.5f);
            float gf = fmaf(0.5f, tanhap(raw[1]), 0.5f);
            float gg = tanhap(raw[2]);
            float go = fmaf(0.5f, tanhap(raw[3]), 0.5f);
            float c  = fmaf(gf, c1[G], gi * gg);
            c1[G] = c;
            Bb[4 * G * PITCH + so1] = go * tanhap(c);
        }
        __syncthreads();

        // ---------------- Layer 2: read B[0..96), write A[64+j2] ----------------
        #pragma unroll
        for (int G = 0; G < 4; ++G) {
            u64 acc[4][4];
            #pragma unroll
            for (int g = 0; g < 4; ++g)
                #pragma unroll
                for (int s = 0; s < 4; ++s) acc[g][s] = 0ULL;

            #pragma unroll
            for (int m = 0; m < 3; ++m)
                #pragma unroll
                for (int s = 0; s < 4; ++s) {
                    ulonglong2 hh =
                        *(const ulonglong2*)(Bb + 4 * G * PITCH + ro2[s] + 4 * m);
                    #pragma unroll
                    for (int g = 0; g < 4; ++g) {
                        fma2(acc[g][s], w2[g][2 * m],     hh.x);
                        fma2(acc[g][s], w2[g][2 * m + 1], hh.y);
                    }
                }

            float raw[4];
            #pragma unroll
            for (int g = 0; g < 4; ++g) {
                float r0, r1, r2, r3;
                { float2 f = unpack2(acc[g][0]); r0 = f.x + f.y; }
                { float2 f = unpack2(acc[g][1]); r1 = f.x + f.y; }
                { float2 f = unpack2(acc[g][2]); r2 = f.x + f.y; }
                { float2 f = unpack2(acc[g][3]); r3 = f.x + f.y; }
                float t1 = r0 + shx(r1, 4);
                float t2 = r2 + shx(r3, 4);
                float tt = t1 + shx(t2, 8);
                raw[g] = tt + shx(tt, 16) + b2r[g];
            }
            float gi = fmaf(0.5f, tanhap(raw[0]), 0.5f);
            float gf = fmaf(0.5f, tanhap(raw[1]), 0.5f);
            float gg = tanhap(raw[2]);
            float go = fmaf(0.5f, tanhap(raw[3]), 0.5f);
            float c  = fmaf(gf, c2[G], gi * gg);
            c2[G] = c;
            if (lane < 16)
                ((float*)&A[0][0])[4 * G * PITCH + so2] = go * tanhap(c);
        }
        __syncthreads();
    };

    for (int t = 0; t < TT; t += 2) {
        step(hcat[0], hcat[1], t);
        step(hcat[1], hcat[0], t + 1);
    }

    // ---- FC head on final h2 (written into hcat[1]) ----
    if (bvalid) {
        const float* hv = &hcat[1][tid][64];
        float o = sfc2b[0];
        #pragma unroll
        for (int f = 0; f < 16; ++f) {
            float acc = sfc1b[f];
            #pragma unroll
            for (int k = 0; k < 32; ++k)
                acc = fmaf(sfc1w[f * 32 + k], hv[k], acc);
            o = fmaf(sfc2w[f], fmaxf(acc, 0.f), o);
        }
        out[b0 + tid] = o;
    }
}

extern "C" void kernel_launch(void* const* d_in, const int* in_sizes, int n_in,
                              void* d_out, int out_size) {
    const float* x    = (const float*)d_in[0];
    const float* Wih1 = (const float*)d_in[1];
    const float* Whh1 = (const float*)d_in[2];
    const float* bih1 = (const float*)d_in[3];
    const float* bhh1 = (const float*)d_in[4];
    const float* Wih2 = (const float*)d_in[5];
    const float* Whh2 = (const float*)d_in[6];
    const float* bih2 = (const float*)d_in[7];
    const float* bhh2 = (const float*)d_in[8];
    const float* fc1w = (const float*)d_in[9];
    const float* fc1b = (const float*)d_in[10];
    const float* fc2w = (const float*)d_in[11];
    const float* fc2b = (const float*)d_in[12];
    float* out = (float*)d_out;

    lstm_fused<<<NCTA, NTH>>>(x, Wih1, Whh1, bih1, bhh1,
                              Wih2, Whh2, bih2, bhh2,
                              fc1w, fc1b, fc2w, fc2b, out);
}

// round 6
// speedup vs baseline: 2.0623x; 1.0117x over previous
#include <cuda_runtime.h>

// R6: R5 + single barrier per step (L2(t) and L1(t+1) fused into one
// barrier-free region) + 32-step double-buffered x chunk in smem.
// 147 CTAs x 256 thr, weights in registers, tanh.approx activations.

typedef unsigned long long u64;

#define TT     512
#define NBR    14
#define NBP    16
#define NTH    256
#define BTOT   2048
#define NCTA   147
#define PITCH  104

__device__ __forceinline__ u64 pack2(float lo, float hi) {
    u64 r; asm("mov.b64 %0, {%1, %2};" : "=l"(r) : "f"(lo), "f"(hi)); return r;
}
__device__ __forceinline__ float2 unpack2(u64 a) {
    float2 r; asm("mov.b64 {%0, %1}, %2;" : "=f"(r.x), "=f"(r.y) : "l"(a)); return r;
}
__device__ __forceinline__ void fma2(u64 &d, u64 a, u64 b) {
    asm("fma.rn.f32x2 %0, %1, %2, %0;" : "+l"(d) : "l"(a), "l"(b));
}
__device__ __forceinline__ float tanhap(float x) {
    float r; asm("tanh.approx.f32 %0, %1;" : "=f"(r) : "f"(x)); return r;
}
__device__ __forceinline__ float shx(float v, int m) {
    return __shfl_xor_sync(0xffffffffu, v, m);
}

__global__ __launch_bounds__(NTH, 1)
void lstm_fused(const float* __restrict__ x,
                const float* __restrict__ Wih1, const float* __restrict__ Whh1,
                const float* __restrict__ bih1, const float* __restrict__ bhh1,
                const float* __restrict__ Wih2, const float* __restrict__ Whh2,
                const float* __restrict__ bih2, const float* __restrict__ bhh2,
                const float* __restrict__ fc1w, const float* __restrict__ fc1b,
                const float* __restrict__ fc2w, const float* __restrict__ fc2b,
                float* __restrict__ out)
{
    __shared__ __align__(16) float  hcat[2][NBP][PITCH];
    __shared__ __align__(16) float4 xchunk[2][32][NBP];   // 32 steps x 16 batch x 4
    __shared__ float sfc1w[512], sfc1b[16], sfc2w[16], sfc2b[1];

    const int tid  = threadIdx.x;
    const int lane = tid & 31;
    const int wg   = tid >> 5;
    const int b0   = blockIdx.x * NBR;
    const bool bvalid = (tid < NBR) && (b0 + tid < BTOT);

    // L1 roles: lane = jslot(3b) | ks1(2b)
    const int jslot = lane & 7;
    const int ks1   = lane >> 3;
    const int j1    = wg * 8 + jslot;
    // L2 roles: lane = js2(2b) | ks2(3b)
    const int js2 = lane & 3;
    const int ks2 = (lane >> 2) & 7;
    const int q2  = ks2 & 3;
    const int j2  = wg * 4 + js2;

    // ---- weights -> registers (sigmoid gates pre-halved) ----
    u64 w1[4][8], w2[4][6];
    float wxs[4], b1r[4], b2r[4];
    #pragma unroll
    for (int g = 0; g < 4; ++g) {
        const float sc = (g == 2) ? 1.f : 0.5f;
        const int r1 = g * 64 + j1;
        #pragma unroll
        for (int m = 0; m < 8; ++m) {
            int k = 16 * ks1 + 2 * m;
            w1[g][m] = pack2(sc * Whh1[r1 * 64 + k], sc * Whh1[r1 * 64 + k + 1]);
        }
        wxs[g] = sc * Wih1[r1 * 4 + ks1];
        b1r[g] = sc * (bih1[r1] + bhh1[r1]);

        const int r2 = g * 32 + j2;
        #pragma unroll
        for (int m = 0; m < 6; ++m) {
            int k = 12 * ks2 + 2 * m;
            float lo = (k < 64)     ? Wih2[r2 * 64 + k]     : Whh2[r2 * 32 + k - 64];
            float hi = (k + 1 < 64) ? Wih2[r2 * 64 + k + 1] : Whh2[r2 * 32 + k - 63];
            w2[g][m] = pack2(sc * lo, sc * hi);
        }
        b2r[g] = sc * (bih2[r2] + bhh2[r2]);
    }

    // per-thread row offsets (float elements)
    int ro1[4], ro2[4], rox[4];
    #pragma unroll
    for (int s = 0; s < 4; ++s) {
        ro1[s] = (ks1 ^ s) * PITCH + 16 * ks1;
        ro2[s] = (q2  ^ s) * PITCH + 12 * ks2;
        rox[s] = (ks1 ^ s) * 4 + ks1;       // into a 16x4 x-slab
    }
    const int so1 = ks1 * PITCH + j1;
    const int so2 = q2 * PITCH + 64 + j2;

    // ---- x chunk loader: 32 steps starting at tbase into buffer buf ----
    auto loadchunk = [&](int buf, int tbase) {
        #pragma unroll 2
        for (int idx = tid; idx < 32 * NBR; idx += NTH) {   // 448 float4s
            int b = idx >> 5, tq = idx & 31;
            float4 v = make_float4(0.f, 0.f, 0.f, 0.f);
            if (b0 + b < BTOT)
                v = *(const float4*)(x + ((size_t)(b0 + b) * TT + tbase + tq) * 4);
            xchunk[buf][tq][b] = v;
        }
    };

    // ---- smem init ----
    for (int i = tid; i < 2 * NBP * PITCH; i += NTH) ((float*)hcat)[i] = 0.f;
    for (int i = tid; i < 512;             i += NTH) sfc1w[i] = fc1w[i];
    if (tid < 16) sfc1b[tid] = fc1b[tid];
    if (tid < 16) sfc2w[tid] = fc2w[tid];
    if (tid == 0) sfc2b[0] = fc2b[0];
    // zero padding rows (b=14,15) of both x buffers
    if (tid < 128) {
        int buf = tid >> 6, tq = (tid >> 1) & 31, b = 14 + (tid & 1);
        xchunk[buf][tq][b] = make_float4(0.f, 0.f, 0.f, 0.f);
    }
    loadchunk(0, 0);
    __syncthreads();

    float c1[4] = {0.f, 0.f, 0.f, 0.f};
    float c2[4] = {0.f, 0.f, 0.f, 0.f};

    // halfstep: [maybe chunkload for t+1 window]; L1(t); BAR; L2(t)  (no tail BAR)
    auto halfstep = [&](float (&A)[NBP][PITCH], float (&B)[NBP][PITCH], int t) {
        if (((t + 1) & 31) == 0 && (t + 1) < TT)
            loadchunk(((t + 1) >> 5) & 1, t + 1);

        const float* Ab = &A[0][0];
        float*       Bb = &B[0][0];
        const float* Xb = (const float*)&xchunk[(t >> 5) & 1][t & 31][0];

        // ---------------- Layer 1: read A[0..64), write B[j1] ----------------
        #pragma unroll
        for (int G = 0; G < 4; ++G) {
            u64 acc[4][4];
            #pragma unroll
            for (int g = 0; g < 4; ++g)
                #pragma unroll
                for (int s = 0; s < 4; ++s) acc[g][s] = 0ULL;

            #pragma unroll
            for (int m = 0; m < 4; ++m)
                #pragma unroll
                for (int s = 0; s < 4; ++s) {
                    ulonglong2 hh =
                        *(const ulonglong2*)(Ab + 4 * G * PITCH + ro1[s] + 4 * m);
                    #pragma unroll
                    for (int g = 0; g < 4; ++g) {
                        fma2(acc[g][s], w1[g][2 * m],     hh.x);
                        fma2(acc[g][s], w1[g][2 * m + 1], hh.y);
                    }
                }

            float xv[4];
            #pragma unroll
            for (int s = 0; s < 4; ++s) xv[s] = Xb[16 * G + rox[s]];

            float raw[4];
            #pragma unroll
            for (int g = 0; g < 4; ++g) {
                float r0, r1, r2, r3;
                { float2 f = unpack2(acc[g][0]); r0 = f.x + f.y; }
                { float2 f = unpack2(acc[g][1]); r1 = f.x + f.y; }
                { float2 f = unpack2(acc[g][2]); r2 = f.x + f.y; }
                { float2 f = unpack2(acc[g][3]); r3 = f.x + f.y; }
                r0 = fmaf(wxs[g], xv[0], r0);
                r1 = fmaf(wxs[g], xv[1], r1);
                r2 = fmaf(wxs[g], xv[2], r2);
                r3 = fmaf(wxs[g], xv[3], r3);
                float t1 = r0 + shx(r1, 8);
                float t2 = r2 + shx(r3, 8);
                raw[g] = t1 + shx(t2, 16) + b1r[g];
            }
            float gi = fmaf(0.5f, tanhap(raw[0]), 0.5f);
            float gf = fmaf(0.5f, tanhap(raw[1]), 0.5f);
            float gg = tanhap(raw[2]);
            float go = fmaf(0.5f, tanhap(raw[3]), 0.5f);
            float c  = fmaf(gf, c1[G], gi * gg);
            c1[G] = c;
            Bb[4 * G * PITCH + so1] = go * tanhap(c);
        }
        __syncthreads();

        // ---------------- Layer 2: read B[0..96), write A[64+j2] ----------------
        #pragma unroll
        for (int G = 0; G < 4; ++G) {
            u64 acc[4][4];
            #pragma unroll
            for (int g = 0; g < 4; ++g)
                #pragma unroll
                for (int s = 0; s < 4; ++s) acc[g][s] = 0ULL;

            #pragma unroll
            for (int m = 0; m < 3; ++m)
                #pragma unroll
                for (int s = 0; s < 4; ++s) {
                    ulonglong2 hh =
                        *(const ulonglong2*)(Bb + 4 * G * PITCH + ro2[s] + 4 * m);
                    #pragma unroll
                    for (int g = 0; g < 4; ++g) {
                        fma2(acc[g][s], w2[g][2 * m],     hh.x);
                        fma2(acc[g][s], w2[g][2 * m + 1], hh.y);
                    }
                }

            float raw[4];
            #pragma unroll
            for (int g = 0; g < 4; ++g) {
                float r0, r1, r2, r3;
                { float2 f = unpack2(acc[g][0]); r0 = f.x + f.y; }
                { float2 f = unpack2(acc[g][1]); r1 = f.x + f.y; }
                { float2 f = unpack2(acc[g][2]); r2 = f.x + f.y; }
                { float2 f = unpack2(acc[g][3]); r3 = f.x + f.y; }
                float t1 = r0 + shx(r1, 4);
                float t2 = r2 + shx(r3, 4);
                float tt = t1 + shx(t2, 8);
                raw[g] = tt + shx(tt, 16) + b2r[g];
            }
            float gi = fmaf(0.5f, tanhap(raw[0]), 0.5f);
            float gf = fmaf(0.5f, tanhap(raw[1]), 0.5f);
            float gg = tanhap(raw[2]);
            float go = fmaf(0.5f, tanhap(raw[3]), 0.5f);
            float c  = fmaf(gf, c2[G], gi * gg);
            c2[G] = c;
            if (lane < 16)
                ((float*)&A[0][0])[4 * G * PITCH + so2] = go * tanhap(c);
        }
        // no trailing barrier: L2(t) and L1(t+1) are race-free (disjoint ranges)
    };

    for (int t = 0; t < TT; t += 2) {
        halfstep(hcat[0], hcat[1], t);
        halfstep(hcat[1], hcat[0], t + 1);
    }

    __syncthreads();

    // ---- FC head on final h2 (in hcat[1][.][64:96]) ----
    if (bvalid) {
        const float* hv = &hcat[1][tid][64];
        float o = sfc2b[0];
        #pragma unroll
        for (int f = 0; f < 16; ++f) {
            float acc = sfc1b[f];
            #pragma unroll
            for (int k = 0; k < 32; ++k)
                acc = fmaf(sfc1w[f * 32 + k], hv[k], acc);
            o = fmaf(sfc2w[f], fmaxf(acc, 0.f), o);
        }
        out[b0 + tid] = o;
    }
}

extern "C" void kernel_launch(void* const* d_in, const int* in_sizes, int n_in,
                              void* d_out, int out_size) {
    const float* x    = (const float*)d_in[0];
    const float* Wih1 = (const float*)d_in[1];
    const float* Whh1 = (const float*)d_in[2];
    const float* bih1 = (const float*)d_in[3];
    const float* bhh1 = (const float*)d_in[4];
    const float* Wih2 = (const float*)d_in[5];
    const float* Whh2 = (const float*)d_in[6];
    const float* bih2 = (const float*)d_in[7];
    const float* bhh2 = (const float*)d_in[8];
    const float* fc1w = (const float*)d_in[9];
    const float* fc1b = (const float*)d_in[10];
    const float* fc2w = (const float*)d_in[11];
    const float* fc2b = (const float*)d_in[12];
    float* out = (float*)d_out;

    lstm_fused<<<NCTA, NTH>>>(x, Wih1, Whh1, bih1, bhh1,
                              Wih2, Whh2, bih2, bhh2,
                              fc1w, fc1b, fc2w, fc2b, out);
}

// round 7
// speedup vs baseline: 2.1854x; 1.0597x over previous
#include <cuda_runtime.h>

// R7: cross-layer warp specialization. Warps 0-7 = Layer1 (w1 in regs),
// warps 8-15 = Layer2 (w2 in regs), 1-step software pipeline, 1 barrier/slot.
// 147 CTAs x 512 thr, <=128 regs/thread -> 4 warps/SMSP.

typedef unsigned long long u64;

#define TT     512
#define NBR    14
#define NBP    16
#define NTH    512
#define BTOT   2048
#define NCTA   147
#define PITCH  104

__device__ __forceinline__ u64 pack2(float lo, float hi) {
    u64 r; asm("mov.b64 %0, {%1, %2};" : "=l"(r) : "f"(lo), "f"(hi)); return r;
}
__device__ __forceinline__ float2 unpack2(u64 a) {
    float2 r; asm("mov.b64 {%0, %1}, %2;" : "=f"(r.x), "=f"(r.y) : "l"(a)); return r;
}
__device__ __forceinline__ void fma2(u64 &d, u64 a, u64 b) {
    asm("fma.rn.f32x2 %0, %1, %2, %0;" : "+l"(d) : "l"(a), "l"(b));
}
__device__ __forceinline__ float tanhap(float x) {
    float r; asm("tanh.approx.f32 %0, %1;" : "=f"(r) : "f"(x)); return r;
}
__device__ __forceinline__ float shx(float v, int m) {
    return __shfl_xor_sync(0xffffffffu, v, m);
}

__global__ __launch_bounds__(NTH, 1)
void lstm_fused(const float* __restrict__ x,
                const float* __restrict__ Wih1, const float* __restrict__ Whh1,
                const float* __restrict__ bih1, const float* __restrict__ bhh1,
                const float* __restrict__ Wih2, const float* __restrict__ Whh2,
                const float* __restrict__ bih2, const float* __restrict__ bhh2,
                const float* __restrict__ fc1w, const float* __restrict__ fc1b,
                const float* __restrict__ fc2w, const float* __restrict__ fc2b,
                float* __restrict__ out)
{
    __shared__ __align__(16) float  hcat[2][NBP][PITCH];
    __shared__ __align__(16) float4 xchunk[2][32][NBP];
    __shared__ float sfc1w[512], sfc1b[16], sfc2w[16], sfc2b[1];

    const int tid  = threadIdx.x;
    const int lane = tid & 31;
    const int wid  = tid >> 5;            // 0..15
    const int b0   = blockIdx.x * NBR;
    const bool bvalid = (tid < NBR) && (b0 + tid < BTOT);

    // ---- smem init (all threads) ----
    for (int i = tid; i < 2 * NBP * PITCH; i += NTH) ((float*)hcat)[i] = 0.f;
    for (int i = tid; i < 512;             i += NTH) sfc1w[i] = fc1w[i];
    if (tid < 16) sfc1b[tid] = fc1b[tid];
    if (tid < 16) sfc2w[tid] = fc2w[tid];
    if (tid == 0) sfc2b[0] = fc2b[0];
    if (tid < 128) {   // zero x padding rows (b=14,15), both buffers
        int buf = tid >> 6, tq = (tid >> 1) & 31, b = 14 + (tid & 1);
        xchunk[buf][tq][b] = make_float4(0.f, 0.f, 0.f, 0.f);
    }

    if (wid < 8) {
        // ================= Layer-1 warps =================
        const int wg    = wid;
        const int jslot = lane & 7;
        const int ks1   = lane >> 3;
        const int j1    = wg * 8 + jslot;

        u64 w1[4][8];
        float wxs[4], b1r[4];
        #pragma unroll
        for (int g = 0; g < 4; ++g) {
            const float sc = (g == 2) ? 1.f : 0.5f;
            const int r1 = g * 64 + j1;
            #pragma unroll
            for (int m = 0; m < 8; ++m) {
                int k = 16 * ks1 + 2 * m;
                w1[g][m] = pack2(sc * Whh1[r1 * 64 + k], sc * Whh1[r1 * 64 + k + 1]);
            }
            wxs[g] = sc * Wih1[r1 * 4 + ks1];
            b1r[g] = sc * (bih1[r1] + bhh1[r1]);
        }
        int ro1[4], rox[4];
        #pragma unroll
        for (int s = 0; s < 4; ++s) {
            ro1[s] = (ks1 ^ s) * PITCH + 16 * ks1;
            rox[s] = (ks1 ^ s) * 4 + ks1;
        }
        const int so1 = ks1 * PITCH + j1;

        // x chunk loader (256 L1 threads)
        auto loadchunk = [&](int buf, int tbase) {
            #pragma unroll 2
            for (int idx = tid; idx < 32 * NBR; idx += 256) {
                int b = idx >> 5, tq = idx & 31;
                float4 v = make_float4(0.f, 0.f, 0.f, 0.f);
                if (b0 + b < BTOT)
                    v = *(const float4*)(x + ((size_t)(b0 + b) * TT + tbase + tq) * 4);
                xchunk[buf][tq][b] = v;
            }
        };
        loadchunk(0, 0);

        float c1[4] = {0.f, 0.f, 0.f, 0.f};
        __syncthreads();

        for (int s = 0; s <= TT; ++s) {
            if (((s + 1) & 31) == 0 && (s + 1) < TT)
                loadchunk(((s + 1) >> 5) & 1, s + 1);

            if (s < TT) {
                const float* Ab = &hcat[(s + 1) & 1][0][0];   // read h1(s-1)
                float*       Bb = &hcat[s & 1][0][0];         // write h1(s)
                const float* Xb = (const float*)&xchunk[(s >> 5) & 1][s & 31][0];

                #pragma unroll
                for (int G = 0; G < 4; ++G) {
                    u64 acc[4][4];
                    #pragma unroll
                    for (int g = 0; g < 4; ++g)
                        #pragma unroll
                        for (int q = 0; q < 4; ++q) acc[g][q] = 0ULL;

                    #pragma unroll
                    for (int m = 0; m < 4; ++m)
                        #pragma unroll
                        for (int q = 0; q < 4; ++q) {
                            ulonglong2 hh =
                                *(const ulonglong2*)(Ab + 4 * G * PITCH + ro1[q] + 4 * m);
                            #pragma unroll
                            for (int g = 0; g < 4; ++g) {
                                fma2(acc[g][2 * (m & 1) + (q & 1)], w1[g][2 * m],     hh.x);
                                fma2(acc[g][2 * (m & 1) + (q & 1)], w1[g][2 * m + 1], hh.y);
                            }
                        }
                    // NOTE: the acc-slot trick above would break batch identity;
                    // keep the straightforward per-q accumulation instead.
                    (void)0;
                    // recompute properly (per-q accumulators)
                    #pragma unroll
                    for (int g = 0; g < 4; ++g)
                        #pragma unroll
                        for (int q = 0; q < 4; ++q) acc[g][q] = 0ULL;
                    #pragma unroll
                    for (int m = 0; m < 4; ++m)
                        #pragma unroll
                        for (int q = 0; q < 4; ++q) {
                            ulonglong2 hh =
                                *(const ulonglong2*)(Ab + 4 * G * PITCH + ro1[q] + 4 * m);
                            #pragma unroll
                            for (int g = 0; g < 4; ++g) {
                                fma2(acc[g][q], w1[g][2 * m],     hh.x);
                                fma2(acc[g][q], w1[g][2 * m + 1], hh.y);
                            }
                        }

                    float xv[4];
                    #pragma unroll
                    for (int q = 0; q < 4; ++q) xv[q] = Xb[16 * G + rox[q]];

                    float raw[4];
                    #pragma unroll
                    for (int g = 0; g < 4; ++g) {
                        float r0, r1, r2, r3;
                        { float2 f = unpack2(acc[g][0]); r0 = f.x + f.y; }
                        { float2 f = unpack2(acc[g][1]); r1 = f.x + f.y; }
                        { float2 f = unpack2(acc[g][2]); r2 = f.x + f.y; }
                        { float2 f = unpack2(acc[g][3]); r3 = f.x + f.y; }
                        r0 = fmaf(wxs[g], xv[0], r0);
                        r1 = fmaf(wxs[g], xv[1], r1);
                        r2 = fmaf(wxs[g], xv[2], r2);
                        r3 = fmaf(wxs[g], xv[3], r3);
                        float t1 = r0 + shx(r1, 8);
                        float t2 = r2 + shx(r3, 8);
                        raw[g] = t1 + shx(t2, 16) + b1r[g];
                    }
                    float gi = fmaf(0.5f, tanhap(raw[0]), 0.5f);
                    float gf = fmaf(0.5f, tanhap(raw[1]), 0.5f);
                    float gg = tanhap(raw[2]);
                    float go = fmaf(0.5f, tanhap(raw[3]), 0.5f);
                    float c  = fmaf(gf, c1[G], gi * gg);
                    c1[G] = c;
                    Bb[4 * G * PITCH + so1] = go * tanhap(c);
                }
            }
            __syncthreads();
        }
    } else {
        // ================= Layer-2 warps =================
        const int wg  = wid - 8;
        const int js2 = lane & 3;
        const int ks2 = (lane >> 2) & 7;
        const int q2  = ks2 & 3;
        const int j2  = wg * 4 + js2;

        u64 w2[4][6];
        float b2r[4];
        #pragma unroll
        for (int g = 0; g < 4; ++g) {
            const float sc = (g == 2) ? 1.f : 0.5f;
            const int r2 = g * 32 + j2;
            #pragma unroll
            for (int m = 0; m < 6; ++m) {
                int k = 12 * ks2 + 2 * m;
                float lo = (k < 64)     ? Wih2[r2 * 64 + k]     : Whh2[r2 * 32 + k - 64];
                float hi = (k + 1 < 64) ? Wih2[r2 * 64 + k + 1] : Whh2[r2 * 32 + k - 63];
                w2[g][m] = pack2(sc * lo, sc * hi);
            }
            b2r[g] = sc * (bih2[r2] + bhh2[r2]);
        }
        int ro2[4];
        #pragma unroll
        for (int q = 0; q < 4; ++q)
            ro2[q] = (q2 ^ q) * PITCH + 12 * ks2;
        const int so2 = q2 * PITCH + 64 + j2;

        float c2[4] = {0.f, 0.f, 0.f, 0.f};
        __syncthreads();

        for (int s = 0; s <= TT; ++s) {
            if (s >= 1) {
                // compute h2(s-1): read h1(s-1)+h2(s-2) from buffer (s+1)&1,
                // write h2(s-1) into buffer s&1 [64:96)
                const float* Rb = &hcat[(s + 1) & 1][0][0];
                float*       Wb = &hcat[s & 1][0][0];

                #pragma unroll
                for (int G = 0; G < 4; ++G) {
                    u64 acc[4][4];
                    #pragma unroll
                    for (int g = 0; g < 4; ++g)
                        #pragma unroll
                        for (int q = 0; q < 4; ++q) acc[g][q] = 0ULL;

                    #pragma unroll
                    for (int m = 0; m < 3; ++m)
                        #pragma unroll
                        for (int q = 0; q < 4; ++q) {
                            ulonglong2 hh =
                                *(const ulonglong2*)(Rb + 4 * G * PITCH + ro2[q] + 4 * m);
                            #pragma unroll
                            for (int g = 0; g < 4; ++g) {
                                fma2(acc[g][q], w2[g][2 * m],     hh.x);
                                fma2(acc[g][q], w2[g][2 * m + 1], hh.y);
                            }
                        }

                    float raw[4];
                    #pragma unroll
                    for (int g = 0; g < 4; ++g) {
                        float r0, r1, r2, r3;
                        { float2 f = unpack2(acc[g][0]); r0 = f.x + f.y; }
                        { float2 f = unpack2(acc[g][1]); r1 = f.x + f.y; }
                        { float2 f = unpack2(acc[g][2]); r2 = f.x + f.y; }
                        { float2 f = unpack2(acc[g][3]); r3 = f.x + f.y; }
                        float t1 = r0 + shx(r1, 4);
                        float t2 = r2 + shx(r3, 4);
                        float tt = t1 + shx(t2, 8);
                        raw[g] = tt + shx(tt, 16) + b2r[g];
                    }
                    float gi = fmaf(0.5f, tanhap(raw[0]), 0.5f);
                    float gf = fmaf(0.5f, tanhap(raw[1]), 0.5f);
                    float gg = tanhap(raw[2]);
                    float go = fmaf(0.5f, tanhap(raw[3]), 0.5f);
                    float c  = fmaf(gf, c2[G], gi * gg);
                    c2[G] = c;
                    if (lane < 16)
                        Wb[4 * G * PITCH + so2] = go * tanhap(c);
                }
            }
            __syncthreads();
        }
    }

    // ---- FC head: final h2(TT-1) is in hcat[TT & 1] = hcat[0], cols [64:96) ----
    if (bvalid) {
        const float* hv = &hcat[TT & 1][tid][64];
        float o = sfc2b[0];
        #pragma unroll
        for (int f = 0; f < 16; ++f) {
            float acc = sfc1b[f];
            #pragma unroll
            for (int k = 0; k < 32; ++k)
                acc = fmaf(sfc1w[f * 32 + k], hv[k], acc);
            o = fmaf(sfc2w[f], fmaxf(acc, 0.f), o);
        }
        out[b0 + tid] = o;
    }
}

extern "C" void kernel_launch(void* const* d_in, const int* in_sizes, int n_in,
                              void* d_out, int out_size) {
    const float* x    = (const float*)d_in[0];
    const float* Wih1 = (const float*)d_in[1];
    const float* Whh1 = (const float*)d_in[2];
    const float* bih1 = (const float*)d_in[3];
    const float* bhh1 = (const float*)d_in[4];
    const float* Wih2 = (const float*)d_in[5];
    const float* Whh2 = (const float*)d_in[6];
    const float* bih2 = (const float*)d_in[7];
    const float* bhh2 = (const float*)d_in[8];
    const float* fc1w = (const float*)d_in[9];
    const float* fc1b = (const float*)d_in[10];
    const float* fc2w = (const float*)d_in[11];
    const float* fc2b = (const float*)d_in[12];
    float* out = (float*)d_out;

    lstm_fused<<<NCTA, NTH>>>(x, Wih1, Whh1, bih1, bhh1,
                              Wih2, Whh2, bih2, bhh2,
                              fc1w, fc1b, fc2w, fc2b, out);
}